// round 4
// baseline (speedup 1.0000x reference)
#include <cuda_runtime.h>

#define BH 64
typedef unsigned long long u64;

// Scratch (device globals)
__device__ float g_Q[BH*16*1024];
__device__ float g_K[BH*16*1024];
__device__ float g_V[BH*16*1024];
__device__ float g_Hn[2*BH*16*1024];  // unnormalized numerators, [z][bh][v][l]
__device__ float g_Hs[2*BH*1024];     // colsums, [z][bh][l]

__device__ __forceinline__ void fma2(u64 &d, u64 a, u64 b) {
    asm("fma.rn.f32x2 %0, %1, %2, %0;" : "+l"(d) : "l"(a), "l"(b));
}
__device__ __forceinline__ void add2(u64 &d, u64 a) {
    asm("add.rn.f32x2 %0, %1, %0;" : "+l"(d) : "l"(a));
}
__device__ __forceinline__ u64 pack2(float lo, float hi) {
    u64 r; asm("mov.b64 %0, {%1, %2};" : "=l"(r) : "f"(lo), "f"(hi)); return r;
}
__device__ __forceinline__ float2 unpack2(u64 v) {
    float2 r; asm("mov.b64 {%0, %1}, %2;" : "=f"(r.x), "=f"(r.y) : "l"(v)); return r;
}
__device__ __forceinline__ u64 dup2(float v) { return pack2(v, v); }
__device__ __forceinline__ float ex2(float x) {
    float y; asm("ex2.approx.ftz.f32 %0, %1;" : "=f"(y) : "f"(x)); return y;
}

// ---------------------------------------------------------------------------
// Kernel A: QKV projection. grid (64 bh, 8 l-chunks of 128, 2 row-halves),
// 128 threads. Each CTA computes 24 of the 48 QKV rows for its l-chunk.
// Thread tile: 3 rows x 4 strided col-pairs (cp = colg + 16p), conflict-free.
// smem 28KB -> high occupancy.
// ---------------------------------------------------------------------------
__global__ __launch_bounds__(128) void qkv_kernel(
    const float* __restrict__ x,
    const float* __restrict__ Wq,
    const float* __restrict__ Wk,
    const float* __restrict__ Wv)
{
    extern __shared__ char sm[];
    float* ws = (float*)sm;                   // [24][128] 12KB
    float* xs = (float*)(sm + 24*128*4);      // [32][128] 16KB

    int bh = blockIdx.x, b = bh >> 3, h = bh & 7;
    int l0 = blockIdx.y * 128;
    int z  = blockIdx.z;                      // 0: rows 0..23, 1: rows 24..47
    int tid = threadIdx.x;

    for (int e = tid; e < 24*128; e += 128) {
        int r = e >> 7, d = e & 127;
        int gr = z*24 + r;
        const float* W = (gr < 16) ? Wq : ((gr < 32) ? Wk : Wv);
        ws[e] = W[((h*8 + b)*16 + (gr & 15))*128 + d];
    }

    int rowg = tid >> 4, colg = tid & 15;   // 8 x 16
    int r0 = rowg*3;

    u64 acc[3][4] = {};
    for (int ch = 0; ch < 4; ch++) {
        __syncthreads();
        for (int idx = tid; idx < 1024; idx += 128) {
            int dd = idx >> 5, c4 = (idx & 31) * 4;
            *(float4*)(xs + dd*128 + c4) =
                *(const float4*)(x + (b*128 + ch*32 + dd)*1024 + l0 + c4);
        }
        __syncthreads();
        #pragma unroll 8
        for (int dd = 0; dd < 32; dd++) {
            u64 xa[4];
            #pragma unroll
            for (int p = 0; p < 4; p++)
                xa[p] = *(const u64*)(xs + dd*128 + (colg + 16*p)*2);
            #pragma unroll
            for (int r = 0; r < 3; r++) {
                u64 w = dup2(ws[(r0 + r)*128 + ch*32 + dd]);
                #pragma unroll
                for (int p = 0; p < 4; p++) fma2(acc[r][p], w, xa[p]);
            }
        }
    }
    #pragma unroll
    for (int r = 0; r < 3; r++) {
        int gr = z*24 + r0 + r;
        float* dst = (gr < 16) ? g_Q : ((gr < 32) ? g_K : g_V);
        float* base = dst + (bh*16 + (gr & 15))*1024 + l0;
        #pragma unroll
        for (int p = 0; p < 4; p++) {
            float2 a = unpack2(acc[r][p]);
            *(float2*)(base + (colg + 16*p)*2) = a;
        }
    }
}

// ---------------------------------------------------------------------------
// Kernel B: attention. grid (64 bh, 4 j-tiles of 256, 2 i-halves), 128 thr.
// Two-phase per 32-i block. Phase-2 thread tile: 4 v-rows x 4 j-pairs.
// ---------------------------------------------------------------------------
__global__ __launch_bounds__(128) void attn_kernel()
{
    extern __shared__ char sm[];
    u64* Kp = (u64*)sm;                       // [16][128]  16KB
    u64* Ps = (u64*)(sm + 16384);             // [32][128]  32KB
    u64* Qd = (u64*)(sm + 16384 + 32768);     // [16][32]   4KB
    u64* Vd = Qd + 512;                       // [16][32]   4KB

    int bh = blockIdx.x;
    int j0 = blockIdx.y * 256;
    int z  = blockIdx.z;
    int tid = threadIdx.x;
    const float SCL = 0.25f * 1.4426950408889634f;  // scale * log2(e)

    for (int e = tid; e < 2048; e += 128) {
        int k = e >> 7, s = e & 127;
        float2 kv = *(const float2*)(g_K + (bh*16 + k)*1024 + j0 + 2*s);
        Kp[e] = pack2(kv.x * SCL, kv.y * SCL);
    }

    int i_base = z * 512;
    float qf[4], vf[4];
    #pragma unroll
    for (int w = 0; w < 4; w++) {
        int e = tid + w*128, k = e >> 5, ii = e & 31;
        qf[w] = g_Q[(bh*16 + k)*1024 + i_base + ii];
        vf[w] = g_V[(bh*16 + k)*1024 + i_base + ii];
    }

    int ig = tid >> 4, jg = tid & 15;   // phase-1: 8 i-groups x 16 j-slots
    int vg = tid >> 5, pg = tid & 31;   // phase-2: 4 v-groups x 32 j-slots

    u64 acc[4][4] = {};
    u64 sum[4] = {};

    for (int t = 0; t < 16; t++) {
        __syncthreads();
        #pragma unroll
        for (int w = 0; w < 4; w++) {
            int e = tid + w*128;
            Qd[e] = dup2(qf[w]);
            Vd[e] = dup2(vf[w]);
        }
        int tn = (t + 1 < 16) ? t + 1 : 15;
        #pragma unroll
        for (int w = 0; w < 4; w++) {
            int e = tid + w*128, k = e >> 5, ii = e & 31;
            qf[w] = g_Q[(bh*16 + k)*1024 + i_base + tn*32 + ii];
            vf[w] = g_V[(bh*16 + k)*1024 + i_base + tn*32 + ii];
        }
        __syncthreads();

        // phase 1: S = Q^T K (scaled), P = exp2(S) -> Ps
        u64 s[4][8] = {};
        #pragma unroll
        for (int k = 0; k < 16; k++) {
            u64 qr[4];
            #pragma unroll
            for (int r = 0; r < 4; r++) qr[r] = Qd[k*32 + ig*4 + r];
            #pragma unroll
            for (int p = 0; p < 8; p++) {
                u64 kv = Kp[k*128 + p*16 + jg];
                #pragma unroll
                for (int r = 0; r < 4; r++) fma2(s[r][p], qr[r], kv);
            }
        }
        #pragma unroll
        for (int r = 0; r < 4; r++) {
            #pragma unroll
            for (int p = 0; p < 8; p++) {
                float2 sv = unpack2(s[r][p]);
                Ps[(ig*4 + r)*128 + p*16 + jg] = pack2(ex2(sv.x), ex2(sv.y));
            }
        }
        __syncthreads();

        // phase 2: H += V * P; colsum += P.  4 v-rows x 4 j-pairs per thread.
        #pragma unroll 4
        for (int ii = 0; ii < 32; ii++) {
            ulonglong2 Pa = *(const ulonglong2*)(Ps + ii*128 + 2*pg);
            ulonglong2 Pb = *(const ulonglong2*)(Ps + ii*128 + 2*pg + 64);
            add2(sum[0], Pa.x); add2(sum[1], Pa.y);
            add2(sum[2], Pb.x); add2(sum[3], Pb.y);
            #pragma unroll
            for (int r = 0; r < 4; r++) {
                u64 vv = Vd[(vg*4 + r)*32 + ii];
                fma2(acc[r][0], Pa.x, vv);
                fma2(acc[r][1], Pa.y, vv);
                fma2(acc[r][2], Pb.x, vv);
                fma2(acc[r][3], Pb.y, vv);
            }
        }
    }

    int zb = z*64 + bh;
    #pragma unroll
    for (int r = 0; r < 4; r++) {
        int row = (zb*16 + vg*4 + r)*1024;
        float2 a0 = unpack2(acc[r][0]), a1 = unpack2(acc[r][1]);
        float2 a2 = unpack2(acc[r][2]), a3 = unpack2(acc[r][3]);
        *(float4*)(g_Hn + row + j0 + 4*pg)       = make_float4(a0.x, a0.y, a1.x, a1.y);
        *(float4*)(g_Hn + row + j0 + 128 + 4*pg) = make_float4(a2.x, a2.y, a3.x, a3.y);
    }
    if (vg == 0) {
        float2 s0 = unpack2(sum[0]), s1 = unpack2(sum[1]);
        float2 s2 = unpack2(sum[2]), s3 = unpack2(sum[3]);
        *(float4*)(g_Hs + zb*1024 + j0 + 4*pg)       = make_float4(s0.x, s0.y, s1.x, s1.y);
        *(float4*)(g_Hs + zb*1024 + j0 + 128 + 4*pg) = make_float4(s2.x, s2.y, s3.x, s3.y);
    }
}

// ---------------------------------------------------------------------------
// Kernel C: normalize + output projection. grid (8 b, 32 l-chunks of 32), 128 thr.
// Row-pair packed W x dup'd-column x.
// ---------------------------------------------------------------------------
__global__ __launch_bounds__(128) void outproj_kernel(
    const float* __restrict__ Wo, float* __restrict__ out)
{
    extern __shared__ char sm[];
    u64*   wp = (u64*)sm;                          // [64][128] row-pairs 64KB
    u64*   xd = (u64*)(sm + 64*128*8);             // [32][32] dup'd norm. H 8KB
    float* rs = (float*)(sm + 64*128*8 + 32*32*8); // [8][32]  1KB

    int b = blockIdx.x;
    int l0 = blockIdx.y * 32;
    int tid = threadIdx.x;

    for (int e = tid; e < 8192; e += 128) {
        int rp = e >> 7, d = e & 127;
        wp[e] = pack2(Wo[(b*128 + 2*rp    )*128 + d],
                      Wo[(b*128 + 2*rp + 1)*128 + d]);
    }
    for (int e = tid; e < 256; e += 128) {
        int h = e >> 5, c = e & 31;
        float s = g_Hs[(b*8 + h)*1024 + l0 + c] + g_Hs[(64 + b*8 + h)*1024 + l0 + c];
        rs[e] = 1.0f / s;
    }

    int rowg = tid >> 3, colg = tid & 7;   // 16 x 8
    int rp0 = rowg*4;

    u64 acc[4][4] = {};
    for (int ch = 0; ch < 4; ch++) {
        __syncthreads();
        for (int e = tid; e < 1024; e += 128) {
            int dd = e >> 5, c = e & 31;
            int d = ch*32 + dd, h = d >> 4, v = d & 15;
            int row = ((b*8 + h)*16 + v)*1024 + l0 + c;
            float n = g_Hn[row] + g_Hn[row + 1048576];
            xd[dd*32 + c] = dup2(n * rs[h*32 + c]);
        }
        __syncthreads();
        #pragma unroll 8
        for (int dd = 0; dd < 32; dd++) {
            u64 xr[4];
            #pragma unroll
            for (int p = 0; p < 4; p++) xr[p] = xd[dd*32 + colg + 8*p];
            #pragma unroll
            for (int r = 0; r < 4; r++) {
                u64 w = wp[(rp0 + r)*128 + ch*32 + dd];
                #pragma unroll
                for (int p = 0; p < 4; p++) fma2(acc[r][p], w, xr[p]);
            }
        }
    }
    #pragma unroll
    for (int r = 0; r < 4; r++) {
        int row = 2*(rp0 + r);
        #pragma unroll
        for (int p = 0; p < 4; p++) {
            float2 a = unpack2(acc[r][p]);   // (row, row+1) at column c
            int c = colg + 8*p;
            out[(b*128 + row    )*1024 + l0 + c] = a.x;
            out[(b*128 + row + 1)*1024 + l0 + c] = a.y;
        }
    }
}

// ---------------------------------------------------------------------------
extern "C" void kernel_launch(void* const* d_in, const int* in_sizes, int n_in,
                              void* d_out, int out_size)
{
    const float* x  = (const float*)d_in[0];
    const float* Wq = (const float*)d_in[1];
    const float* Wk = (const float*)d_in[2];
    const float* Wv = (const float*)d_in[3];
    const float* Wo = (const float*)d_in[4];
    float* out = (float*)d_out;

    const int smemA = 24*128*4 + 32*128*4;              // 28672
    const int smemB = 16384 + 32768 + 4096 + 4096;      // 57344
    const int smemC = 64*128*8 + 32*32*8 + 8*32*4;      // 74752
    cudaFuncSetAttribute(qkv_kernel,     cudaFuncAttributeMaxDynamicSharedMemorySize, smemA);
    cudaFuncSetAttribute(attn_kernel,    cudaFuncAttributeMaxDynamicSharedMemorySize, smemB);
    cudaFuncSetAttribute(outproj_kernel, cudaFuncAttributeMaxDynamicSharedMemorySize, smemC);

    qkv_kernel<<<dim3(64, 8, 2), 128, smemA>>>(x, Wq, Wk, Wv);
    attn_kernel<<<dim3(64, 4, 2), 128, smemB>>>();
    outproj_kernel<<<dim3(8, 32), 128, smemC>>>(Wo, out);
}

// round 6
// speedup vs baseline: 1.8062x; 1.8062x over previous
#include <cuda_runtime.h>
#include <cstdint>

typedef unsigned long long u64;
typedef unsigned int u32;
typedef unsigned short u16;

#define BH 64

// Scratch (device globals)
__device__ float g_Q[BH*16*1024];
__device__ float g_K[BH*16*1024];
__device__ float g_V[BH*16*1024];
__device__ float g_H[8*128*1024];        // normalized heads [b][d][l]
// Prebuilt mma.sync fragment images (per-lane order, LDG.128-ready)
__device__ uint4 g_KF[BH*64*32*2];       // [bh][jblk16][lane]{Kh a0..a3 | Kl a0..a3}, *SCL
__device__ uint4 g_QF[BH*128*32];        // [bh][ichunk8][lane]{Qh b0,b1, Ql b0,b1}
__device__ uint4 g_VF[BH*64*32*2];       // [bh][ichunk16][lane]{Vh(v0-7)b0,b1,Vh(v8-15)b0,b1 | Vl same}

// ---------------- helpers ----------------
__device__ __forceinline__ void fma2(u64 &d, u64 a, u64 b) {
    asm("fma.rn.f32x2 %0, %1, %2, %0;" : "+l"(d) : "l"(a), "l"(b));
}
__device__ __forceinline__ u64 pack2(float lo, float hi) {
    u64 r; asm("mov.b64 %0, {%1, %2};" : "=l"(r) : "f"(lo), "f"(hi)); return r;
}
__device__ __forceinline__ float2 unpack2(u64 v) {
    float2 r; asm("mov.b64 {%0, %1}, %2;" : "=f"(r.x), "=f"(r.y) : "l"(v)); return r;
}
__device__ __forceinline__ u64 dup2(float v) { return pack2(v, v); }
__device__ __forceinline__ float ex2(float x) {
    float y; asm("ex2.approx.ftz.f32 %0, %1;" : "=f"(y) : "f"(x)); return y;
}
__device__ __forceinline__ u16 bf16r(float f){ u16 h; asm("cvt.rn.bf16.f32 %0, %1;" : "=h"(h) : "f"(f)); return h; }
__device__ __forceinline__ float bf16f(u16 h){ return __uint_as_float(((u32)h)<<16); }
// packs: upper half = hi arg, lower half = lo arg
__device__ __forceinline__ u32 cvt2bf(float hi, float lo){
    u32 r; asm("cvt.rn.bf16x2.f32 %0, %1, %2;" : "=r"(r) : "f"(hi), "f"(lo)); return r;
}
__device__ __forceinline__ u32 packsplit(float a, float b, u32 &lo_out, float /*dummy*/) { return 0; }

// split two floats -> hi bf16x2 (b in upper, a in lower) and lo bf16x2
__device__ __forceinline__ void split2(float a, float b, u32 &hi, u32 &lo) {
    hi = cvt2bf(b, a);
    float la = a - __uint_as_float(hi << 16);
    float lb = b - __uint_as_float(hi & 0xFFFF0000u);
    lo = cvt2bf(lb, la);
}

__device__ __forceinline__ void mma_bf16(float d[4], const u32 a[4], u32 b0, u32 b1) {
    asm volatile("mma.sync.aligned.m16n8k16.row.col.f32.bf16.bf16.f32 "
        "{%0,%1,%2,%3}, {%4,%5,%6,%7}, {%8,%9}, {%0,%1,%2,%3};"
        : "+f"(d[0]),"+f"(d[1]),"+f"(d[2]),"+f"(d[3])
        : "r"(a[0]),"r"(a[1]),"r"(a[2]),"r"(a[3]), "r"(b0),"r"(b1));
}

// ---------------------------------------------------------------------------
// Kernel A: QKV projection (best FFMA2 version, unchanged).
// ---------------------------------------------------------------------------
__global__ __launch_bounds__(128) void qkv_kernel(
    const float* __restrict__ x,
    const float* __restrict__ Wq,
    const float* __restrict__ Wk,
    const float* __restrict__ Wv)
{
    extern __shared__ char sm[];
    float* ws = (float*)sm;                   // [24][128]
    float* xs = (float*)(sm + 24*128*4);      // [32][128]

    int bh = blockIdx.x, b = bh >> 3, h = bh & 7;
    int l0 = blockIdx.y * 128;
    int z  = blockIdx.z;
    int tid = threadIdx.x;

    for (int e = tid; e < 24*128; e += 128) {
        int r = e >> 7, d = e & 127;
        int gr = z*24 + r;
        const float* W = (gr < 16) ? Wq : ((gr < 32) ? Wk : Wv);
        ws[e] = W[((h*8 + b)*16 + (gr & 15))*128 + d];
    }

    int rowg = tid >> 4, colg = tid & 15;
    int r0 = rowg*3;

    u64 acc[3][4] = {};
    for (int ch = 0; ch < 4; ch++) {
        __syncthreads();
        for (int idx = tid; idx < 1024; idx += 128) {
            int dd = idx >> 5, c4 = (idx & 31) * 4;
            *(float4*)(xs + dd*128 + c4) =
                *(const float4*)(x + (b*128 + ch*32 + dd)*1024 + l0 + c4);
        }
        __syncthreads();
        #pragma unroll 8
        for (int dd = 0; dd < 32; dd++) {
            u64 xa[4];
            #pragma unroll
            for (int p = 0; p < 4; p++)
                xa[p] = *(const u64*)(xs + dd*128 + (colg + 16*p)*2);
            #pragma unroll
            for (int r = 0; r < 3; r++) {
                u64 w = dup2(ws[(r0 + r)*128 + ch*32 + dd]);
                #pragma unroll
                for (int p = 0; p < 4; p++) fma2(acc[r][p], w, xa[p]);
            }
        }
    }
    #pragma unroll
    for (int r = 0; r < 3; r++) {
        int gr = z*24 + r0 + r;
        float* dst = (gr < 16) ? g_Q : ((gr < 32) ? g_K : g_V);
        float* base = dst + (bh*16 + (gr & 15))*1024 + l0;
        #pragma unroll
        for (int p = 0; p < 4; p++) {
            float2 a = unpack2(acc[r][p]);
            *(float2*)(base + (colg + 16*p)*2) = a;
        }
    }
}

// ---------------------------------------------------------------------------
// Kernel P: build split-bf16 mma fragments. grid (64 bh, 8 slices), 256 thr.
// Fragment layouts per PTX ISA m16n8k16 (row.col):
//  A a0=(g,2t..), a1=(g+8,2t..), a2=(g,2t+8..), a3=(g+8,2t+8..)
//  B b0=(k=2t..,n=g), b1=(k=2t+8..,n=g)
// ---------------------------------------------------------------------------
__global__ __launch_bounds__(256) void prep_kernel()
{
    int bh = blockIdx.x, slice = blockIdx.y, tid = threadIdx.x;
    const float SCLF = 0.25f * 1.4426950408889634f;  // scale * log2(e)

    // --- K fragments: A-operand, rows j, cols k (16). 2048 entries/bh.
    {
        int e = slice*256 + tid;
        int blk = e >> 5, lane = e & 31, g = lane >> 2, t = lane & 3;
        int r0 = blk*16 + g, r1 = r0 + 8;
        int k0 = 2*t, k2 = 2*t + 8;
        float f0 = g_K[(bh*16 + k0    )*1024 + r0] * SCLF;
        float f1 = g_K[(bh*16 + k0 + 1)*1024 + r0] * SCLF;
        float f2 = g_K[(bh*16 + k0    )*1024 + r1] * SCLF;
        float f3 = g_K[(bh*16 + k0 + 1)*1024 + r1] * SCLF;
        float f4 = g_K[(bh*16 + k2    )*1024 + r0] * SCLF;
        float f5 = g_K[(bh*16 + k2 + 1)*1024 + r0] * SCLF;
        float f6 = g_K[(bh*16 + k2    )*1024 + r1] * SCLF;
        float f7 = g_K[(bh*16 + k2 + 1)*1024 + r1] * SCLF;
        uint4 hi, lo;
        split2(f0, f1, hi.x, lo.x);
        split2(f2, f3, hi.y, lo.y);
        split2(f4, f5, hi.z, lo.z);
        split2(f6, f7, hi.w, lo.w);
        int idx = ((bh*64 + blk)*32 + lane)*2;
        g_KF[idx] = hi; g_KF[idx + 1] = lo;
    }
    // --- Q fragments: B-operand, i-chunks of 8. 4096 entries/bh.
    for (int s = 0; s < 2; s++) {
        int e = slice*512 + s*256 + tid;
        int ch = e >> 5, lane = e & 31, g = lane >> 2, t = lane & 3;
        int i = ch*8 + g;
        float f0 = g_Q[(bh*16 + 2*t    )*1024 + i];
        float f1 = g_Q[(bh*16 + 2*t + 1)*1024 + i];
        float f2 = g_Q[(bh*16 + 2*t + 8)*1024 + i];
        float f3 = g_Q[(bh*16 + 2*t + 9)*1024 + i];
        uint4 o;
        u32 l0, l1;
        split2(f0, f1, o.x, l0);
        split2(f2, f3, o.y, l1);
        o.z = l0; o.w = l1;
        g_QF[(bh*128 + ch)*32 + lane] = o;
    }
    // --- V fragments: B-operand, i-chunks of 16, n=v halves. 2048 entries/bh.
    {
        int e = slice*256 + tid;
        int c16 = e >> 5, lane = e & 31, g = lane >> 2, t = lane & 3;
        int i0 = c16*16;
        float a0 = g_V[(bh*16 + g    )*1024 + i0 + 2*t];
        float a1 = g_V[(bh*16 + g    )*1024 + i0 + 2*t + 1];
        float a2 = g_V[(bh*16 + g    )*1024 + i0 + 2*t + 8];
        float a3 = g_V[(bh*16 + g    )*1024 + i0 + 2*t + 9];
        float c0 = g_V[(bh*16 + g + 8)*1024 + i0 + 2*t];
        float c1 = g_V[(bh*16 + g + 8)*1024 + i0 + 2*t + 1];
        float c2 = g_V[(bh*16 + g + 8)*1024 + i0 + 2*t + 8];
        float c3 = g_V[(bh*16 + g + 8)*1024 + i0 + 2*t + 9];
        uint4 hi, lo;
        split2(a0, a1, hi.x, lo.x);   // half0 b0
        split2(a2, a3, hi.y, lo.y);   // half0 b1
        split2(c0, c1, hi.z, lo.z);   // half1 b0
        split2(c2, c3, hi.w, lo.w);   // half1 b1
        int idx = ((bh*64 + c16)*32 + lane)*2;
        g_VF[idx] = hi; g_VF[idx + 1] = lo;
    }
}

// ---------------------------------------------------------------------------
// Kernel B: mma.sync flash attention. grid (64 bh, 8 jtiles of 128), 256 thr.
// Warp w owns j-rows [jt*128 + w*16, +16). Iterates 64 i-chunks of 16.
// S = Kh Qh + Kl Qh + Kh Ql ; P = exp2(S) in regs ; O += Ph Vh + Pl Vh + Ph Vl.
// Denominator = register row-sums of exact P (shfl-reduced).
// ---------------------------------------------------------------------------
__global__ __launch_bounds__(256) void attn_kernel()
{
    int bh = blockIdx.x, jt = blockIdx.y, tid = threadIdx.x;
    int w = tid >> 5, lane = tid & 31, g = lane >> 2, t = lane & 3;

    const uint4* kf = g_KF + ((bh*64 + jt*8 + w)*32 + lane)*2;
    uint4 khv = kf[0], klv = kf[1];
    u32 kh[4] = {khv.x, khv.y, khv.z, khv.w};
    u32 kl[4] = {klv.x, klv.y, klv.z, klv.w};

    const uint4* qf = g_QF + bh*128*32 + lane;
    const uint4* vf = g_VF + (bh*64*32 + lane)*2;

    float o0[4] = {}, o1[4] = {};
    float dg = 0.0f, d8 = 0.0f;

    #pragma unroll 2
    for (int c = 0; c < 64; c++) {
        uint4 q0 = qf[(2*c    )*32];
        uint4 q1 = qf[(2*c + 1)*32];
        uint4 va = vf[c*64];
        uint4 vb = vf[c*64 + 1];

        float sa[4] = {0.f,0.f,0.f,0.f}, sb[4] = {0.f,0.f,0.f,0.f};
        mma_bf16(sa, kh, q0.x, q0.y);
        mma_bf16(sa, kl, q0.x, q0.y);
        mma_bf16(sa, kh, q0.z, q0.w);
        mma_bf16(sb, kh, q1.x, q1.y);
        mma_bf16(sb, kl, q1.x, q1.y);
        mma_bf16(sb, kh, q1.z, q1.w);

        float pa0 = ex2(sa[0]), pa1 = ex2(sa[1]), pa2 = ex2(sa[2]), pa3 = ex2(sa[3]);
        float pb0 = ex2(sb[0]), pb1 = ex2(sb[1]), pb2 = ex2(sb[2]), pb3 = ex2(sb[3]);
        dg += (pa0 + pa1) + (pb0 + pb1);
        d8 += (pa2 + pa3) + (pb2 + pb3);

        u32 ph[4], pl[4];
        split2(pa0, pa1, ph[0], pl[0]);
        split2(pa2, pa3, ph[1], pl[1]);
        split2(pb0, pb1, ph[2], pl[2]);
        split2(pb2, pb3, ph[3], pl[3]);

        mma_bf16(o0, ph, va.x, va.y);
        mma_bf16(o0, pl, va.x, va.y);
        mma_bf16(o0, ph, vb.x, vb.y);
        mma_bf16(o1, ph, va.z, va.w);
        mma_bf16(o1, pl, va.z, va.w);
        mma_bf16(o1, ph, vb.z, vb.w);
    }

    dg += __shfl_xor_sync(0xFFFFFFFFu, dg, 1);
    dg += __shfl_xor_sync(0xFFFFFFFFu, dg, 2);
    d8 += __shfl_xor_sync(0xFFFFFFFFu, d8, 1);
    d8 += __shfl_xor_sync(0xFFFFFFFFu, d8, 2);
    float rg = 1.0f / dg, r8 = 1.0f / d8;

    int b = bh >> 3, h = bh & 7;
    int j0 = jt*128 + w*16 + g;
    float* base = g_H + (b*128 + h*16)*1024;
    int v0 = 2*t, v1 = 2*t + 8;
    base[(v0    )*1024 + j0    ] = o0[0] * rg;
    base[(v0 + 1)*1024 + j0    ] = o0[1] * rg;
    base[(v0    )*1024 + j0 + 8] = o0[2] * r8;
    base[(v0 + 1)*1024 + j0 + 8] = o0[3] * r8;
    base[(v1    )*1024 + j0    ] = o1[0] * rg;
    base[(v1 + 1)*1024 + j0    ] = o1[1] * rg;
    base[(v1    )*1024 + j0 + 8] = o1[2] * r8;
    base[(v1 + 1)*1024 + j0 + 8] = o1[3] * r8;
}

// ---------------------------------------------------------------------------
// Kernel C: output projection (best FFMA2 version, reads g_H).
// ---------------------------------------------------------------------------
__global__ __launch_bounds__(128) void outproj_kernel(
    const float* __restrict__ Wo, float* __restrict__ out)
{
    extern __shared__ char sm[];
    u64* wp = (u64*)sm;                  // [64][128] row-pairs
    u64* xd = (u64*)(sm + 64*128*8);     // [32][32] dup'd heads

    int b = blockIdx.x;
    int l0 = blockIdx.y * 32;
    int tid = threadIdx.x;

    for (int e = tid; e < 8192; e += 128) {
        int rp = e >> 7, d = e & 127;
        wp[e] = pack2(Wo[(b*128 + 2*rp    )*128 + d],
                      Wo[(b*128 + 2*rp + 1)*128 + d]);
    }

    int rowg = tid >> 3, colg = tid & 7;
    int rp0 = rowg*4;

    u64 acc[4][4] = {};
    for (int ch = 0; ch < 4; ch++) {
        __syncthreads();
        for (int e = tid; e < 1024; e += 128) {
            int dd = e >> 5, c = e & 31;
            int d = ch*32 + dd;
            xd[dd*32 + c] = dup2(g_H[(b*128 + d)*1024 + l0 + c]);
        }
        __syncthreads();
        #pragma unroll 8
        for (int dd = 0; dd < 32; dd++) {
            u64 xr[4];
            #pragma unroll
            for (int p = 0; p < 4; p++) xr[p] = xd[dd*32 + colg + 8*p];
            #pragma unroll
            for (int r = 0; r < 4; r++) {
                u64 ww = wp[(rp0 + r)*128 + ch*32 + dd];
                #pragma unroll
                for (int p = 0; p < 4; p++) fma2(acc[r][p], ww, xr[p]);
            }
        }
    }
    #pragma unroll
    for (int r = 0; r < 4; r++) {
        int row = 2*(rp0 + r);
        #pragma unroll
        for (int p = 0; p < 4; p++) {
            float2 a = unpack2(acc[r][p]);
            int c = colg + 8*p;
            out[(b*128 + row    )*1024 + l0 + c] = a.x;
            out[(b*128 + row + 1)*1024 + l0 + c] = a.y;
        }
    }
}

// ---------------------------------------------------------------------------
extern "C" void kernel_launch(void* const* d_in, const int* in_sizes, int n_in,
                              void* d_out, int out_size)
{
    const float* x  = (const float*)d_in[0];
    const float* Wq = (const float*)d_in[1];
    const float* Wk = (const float*)d_in[2];
    const float* Wv = (const float*)d_in[3];
    const float* Wo = (const float*)d_in[4];
    float* out = (float*)d_out;

    const int smemA = 24*128*4 + 32*128*4;   // 28672
    const int smemC = 64*128*8 + 32*32*8;    // 73728
    cudaFuncSetAttribute(qkv_kernel,     cudaFuncAttributeMaxDynamicSharedMemorySize, smemA);
    cudaFuncSetAttribute(outproj_kernel, cudaFuncAttributeMaxDynamicSharedMemorySize, smemC);

    qkv_kernel<<<dim3(64, 8, 2), 128, smemA>>>(x, Wq, Wk, Wv);
    prep_kernel<<<dim3(64, 8), 256>>>();
    attn_kernel<<<dim3(64, 8), 256>>>();
    outproj_kernel<<<dim3(8, 32), 128, smemC>>>(Wo, out);
}

// round 7
// speedup vs baseline: 2.2912x; 1.2686x over previous
#include <cuda_runtime.h>
#include <cstdint>

typedef unsigned long long u64;
typedef unsigned int u32;
typedef unsigned short u16;

#define BH 64

// Scratch (device globals)
__device__ float g_Q[BH*16*1024];
__device__ float g_K[BH*16*1024];
__device__ float g_V[BH*16*1024];
// Fragment images (m16n8k16 per-lane order, split bf16 hi/lo)
__device__ uint4 g_XF[8*8*128*32];       // x  B-frags [b][kc][nb][lane]{b0h,b1h,b0l,b1l}
__device__ uint4 g_WF[64*3*8*32*2];      // Wqkv A-frags [bh][mb][kc][lane]{hi,lo}
__device__ uint4 g_WoF[8*8*8*32*2];      // Wo A-frags [b][mb][kc][lane]{hi,lo}
__device__ uint4 g_HF[8*8*128*32];       // H  B-frags [b][kc=h][nb][lane] (written by attn)
__device__ uint4 g_KF[BH*64*32*2];       // attn A-frags (K, *SCL)
__device__ uint4 g_QF[BH*128*32];        // attn B-frags (Q)
__device__ uint4 g_VF[BH*64*32*2];       // attn B-frags (V)

// ---------------- helpers ----------------
__device__ __forceinline__ float ex2(float x) {
    float y; asm("ex2.approx.ftz.f32 %0, %1;" : "=f"(y) : "f"(x)); return y;
}
__device__ __forceinline__ u32 cvt2bf(float hi, float lo){
    u32 r; asm("cvt.rn.bf16x2.f32 %0, %1, %2;" : "=r"(r) : "f"(hi), "f"(lo)); return r;
}
// split (first, second) -> hi bf16x2 (second in upper), lo bf16x2 (residuals)
__device__ __forceinline__ void split2(float a, float b, u32 &hi, u32 &lo) {
    hi = cvt2bf(b, a);
    float la = a - __uint_as_float(hi << 16);
    float lb = b - __uint_as_float(hi & 0xFFFF0000u);
    lo = cvt2bf(lb, la);
}
__device__ __forceinline__ void mma_bf16(float d[4], const u32 a[4], u32 b0, u32 b1) {
    asm volatile("mma.sync.aligned.m16n8k16.row.col.f32.bf16.bf16.f32 "
        "{%0,%1,%2,%3}, {%4,%5,%6,%7}, {%8,%9}, {%0,%1,%2,%3};"
        : "+f"(d[0]),"+f"(d[1]),"+f"(d[2]),"+f"(d[3])
        : "r"(a[0]),"r"(a[1]),"r"(a[2]),"r"(a[3]), "r"(b0),"r"(b1));
}

// ---------------------------------------------------------------------------
// Kernel 1: prep_in — fragment images for x, Wqkv, Wo. grid 512 x 256.
// ---------------------------------------------------------------------------
__global__ __launch_bounds__(256) void prep_in(
    const float* __restrict__ x,
    const float* __restrict__ Wq, const float* __restrict__ Wk,
    const float* __restrict__ Wv, const float* __restrict__ Wo)
{
    int tid = blockIdx.x*256 + threadIdx.x;
    int stride = gridDim.x*256;

    // x B-fragments: 262144 entries
    for (int e = tid; e < 8*8*128*32; e += stride) {
        int lane = e & 31, nb = (e >> 5) & 127, kc = (e >> 12) & 7, b = e >> 15;
        int g = lane >> 2, t = lane & 3;
        const float* xb = x + b*128*1024 + nb*8 + g;
        int d = kc*16 + 2*t;
        float f0 = xb[(d    )*1024], f1 = xb[(d + 1)*1024];
        float f2 = xb[(d + 8)*1024], f3 = xb[(d + 9)*1024];
        uint4 o; u32 l0, l1;
        split2(f0, f1, o.x, l0);
        split2(f2, f3, o.y, l1);
        o.z = l0; o.w = l1;
        g_XF[e] = o;
    }
    // Wqkv A-fragments: 49152 entries
    for (int e = tid; e < 64*3*8*32; e += stride) {
        int lane = e & 31, kc = (e >> 5) & 7;
        int mb = (e >> 8) % 3, bh = (e >> 8) / 3;
        int g = lane >> 2, t = lane & 3;
        int b = bh >> 3, h = bh & 7;
        int m0 = mb*16 + g, m1 = m0 + 8, k0 = kc*16 + 2*t, k2 = k0 + 8;
        const float* Wm0 = (m0 < 16) ? Wq : ((m0 < 32) ? Wk : Wv);
        const float* Wm1 = (m1 < 16) ? Wq : ((m1 < 32) ? Wk : Wv);
        const float* r0p = Wm0 + ((h*8 + b)*16 + (m0 & 15))*128;
        const float* r1p = Wm1 + ((h*8 + b)*16 + (m1 & 15))*128;
        uint4 hi, lo;
        split2(r0p[k0], r0p[k0+1], hi.x, lo.x);
        split2(r1p[k0], r1p[k0+1], hi.y, lo.y);
        split2(r0p[k2], r0p[k2+1], hi.z, lo.z);
        split2(r1p[k2], r1p[k2+1], hi.w, lo.w);
        g_WF[e*2] = hi; g_WF[e*2 + 1] = lo;
    }
    // Wo A-fragments: 16384 entries
    for (int e = tid; e < 8*8*8*32; e += stride) {
        int lane = e & 31, kc = (e >> 5) & 7, mb = (e >> 8) & 7, b = e >> 11;
        int g = lane >> 2, t = lane & 3;
        int m0 = mb*16 + g, m1 = m0 + 8, k0 = kc*16 + 2*t, k2 = k0 + 8;
        const float* W = Wo + b*128*128;
        uint4 hi, lo;
        split2(W[m0*128 + k0], W[m0*128 + k0+1], hi.x, lo.x);
        split2(W[m1*128 + k0], W[m1*128 + k0+1], hi.y, lo.y);
        split2(W[m0*128 + k2], W[m0*128 + k2+1], hi.z, lo.z);
        split2(W[m1*128 + k2], W[m1*128 + k2+1], hi.w, lo.w);
        g_WoF[e*2] = hi; g_WoF[e*2 + 1] = lo;
    }
}

// ---------------------------------------------------------------------------
// Kernel 2: qkv_mma — QKV projection on tensor cores.
// grid (64 bh, 8 l-tiles of 128), 256 thr. Warp: M=48 x N=16 (2 n-blocks).
// ---------------------------------------------------------------------------
__device__ __forceinline__ void store_qkv(int bh, int gr, int col, float v0, float v1) {
    float* dst = (gr < 16) ? g_Q : ((gr < 32) ? g_K : g_V);
    *(float2*)(dst + (bh*16 + (gr & 15))*1024 + col) = make_float2(v0, v1);
}

__global__ __launch_bounds__(256) void qkv_mma()
{
    int bh = blockIdx.x, b = bh >> 3;
    int lt = blockIdx.y;
    int tid = threadIdx.x, w = tid >> 5, lane = tid & 31;
    int g = lane >> 2, t = lane & 3;
    int nb0 = lt*16 + w*2;

    float acc[3][2][4] = {};
    #pragma unroll
    for (int kc = 0; kc < 8; kc++) {
        uint4 B0 = g_XF[((b*8 + kc)*128 + nb0    )*32 + lane];
        uint4 B1 = g_XF[((b*8 + kc)*128 + nb0 + 1)*32 + lane];
        #pragma unroll
        for (int mb = 0; mb < 3; mb++) {
            const uint4* af = g_WF + (((bh*3 + mb)*8 + kc)*32 + lane)*2;
            uint4 Ah = af[0], Al = af[1];
            u32 ah[4] = {Ah.x, Ah.y, Ah.z, Ah.w};
            u32 al[4] = {Al.x, Al.y, Al.z, Al.w};
            mma_bf16(acc[mb][0], ah, B0.x, B0.y);
            mma_bf16(acc[mb][0], al, B0.x, B0.y);
            mma_bf16(acc[mb][0], ah, B0.z, B0.w);
            mma_bf16(acc[mb][1], ah, B1.x, B1.y);
            mma_bf16(acc[mb][1], al, B1.x, B1.y);
            mma_bf16(acc[mb][1], ah, B1.z, B1.w);
        }
    }
    #pragma unroll
    for (int mb = 0; mb < 3; mb++) {
        #pragma unroll
        for (int nbi = 0; nbi < 2; nbi++) {
            int col = (nb0 + nbi)*8 + 2*t;
            int r0 = mb*16 + g;
            store_qkv(bh, r0,     col, acc[mb][nbi][0], acc[mb][nbi][1]);
            store_qkv(bh, r0 + 8, col, acc[mb][nbi][2], acc[mb][nbi][3]);
        }
    }
}

// ---------------------------------------------------------------------------
// Kernel 3: prep_attn — attn fragments from linear Q/K/V (validated R6 layout).
// grid (64 bh, 8 slices), 256 thr.
// ---------------------------------------------------------------------------
__global__ __launch_bounds__(256) void prep_attn()
{
    int bh = blockIdx.x, slice = blockIdx.y, tid = threadIdx.x;
    const float SCLF = 0.25f * 1.4426950408889634f;  // scale * log2(e)

    {   // K A-fragments (scaled)
        int e = slice*256 + tid;
        int blk = e >> 5, lane = e & 31, g = lane >> 2, t = lane & 3;
        int r0 = blk*16 + g, r1 = r0 + 8;
        int k0 = 2*t, k2 = 2*t + 8;
        float f0 = g_K[(bh*16 + k0    )*1024 + r0] * SCLF;
        float f1 = g_K[(bh*16 + k0 + 1)*1024 + r0] * SCLF;
        float f2 = g_K[(bh*16 + k0    )*1024 + r1] * SCLF;
        float f3 = g_K[(bh*16 + k0 + 1)*1024 + r1] * SCLF;
        float f4 = g_K[(bh*16 + k2    )*1024 + r0] * SCLF;
        float f5 = g_K[(bh*16 + k2 + 1)*1024 + r0] * SCLF;
        float f6 = g_K[(bh*16 + k2    )*1024 + r1] * SCLF;
        float f7 = g_K[(bh*16 + k2 + 1)*1024 + r1] * SCLF;
        uint4 hi, lo;
        split2(f0, f1, hi.x, lo.x);
        split2(f2, f3, hi.y, lo.y);
        split2(f4, f5, hi.z, lo.z);
        split2(f6, f7, hi.w, lo.w);
        int idx = ((bh*64 + blk)*32 + lane)*2;
        g_KF[idx] = hi; g_KF[idx + 1] = lo;
    }
    for (int s = 0; s < 2; s++) {  // Q B-fragments
        int e = slice*512 + s*256 + tid;
        int ch = e >> 5, lane = e & 31, g = lane >> 2, t = lane & 3;
        int i = ch*8 + g;
        float f0 = g_Q[(bh*16 + 2*t    )*1024 + i];
        float f1 = g_Q[(bh*16 + 2*t + 1)*1024 + i];
        float f2 = g_Q[(bh*16 + 2*t + 8)*1024 + i];
        float f3 = g_Q[(bh*16 + 2*t + 9)*1024 + i];
        uint4 o; u32 l0, l1;
        split2(f0, f1, o.x, l0);
        split2(f2, f3, o.y, l1);
        o.z = l0; o.w = l1;
        g_QF[(bh*128 + ch)*32 + lane] = o;
    }
    {   // V B-fragments
        int e = slice*256 + tid;
        int c16 = e >> 5, lane = e & 31, g = lane >> 2, t = lane & 3;
        int i0 = c16*16;
        float a0 = g_V[(bh*16 + g    )*1024 + i0 + 2*t];
        float a1 = g_V[(bh*16 + g    )*1024 + i0 + 2*t + 1];
        float a2 = g_V[(bh*16 + g    )*1024 + i0 + 2*t + 8];
        float a3 = g_V[(bh*16 + g    )*1024 + i0 + 2*t + 9];
        float c0 = g_V[(bh*16 + g + 8)*1024 + i0 + 2*t];
        float c1 = g_V[(bh*16 + g + 8)*1024 + i0 + 2*t + 1];
        float c2 = g_V[(bh*16 + g + 8)*1024 + i0 + 2*t + 8];
        float c3 = g_V[(bh*16 + g + 8)*1024 + i0 + 2*t + 9];
        uint4 hi, lo;
        split2(a0, a1, hi.x, lo.x);
        split2(a2, a3, hi.y, lo.y);
        split2(c0, c1, hi.z, lo.z);
        split2(c2, c3, hi.w, lo.w);
        int idx = ((bh*64 + c16)*32 + lane)*2;
        g_VF[idx] = hi; g_VF[idx + 1] = lo;
    }
}

// ---------------------------------------------------------------------------
// Kernel 4: attn — mma.sync flash attention (R6 core); epilogue emits
// normalized H directly as outproj B-fragments (g_HF).
// grid (64 bh, 8 jtiles of 128), 256 thr.
// ---------------------------------------------------------------------------
__global__ __launch_bounds__(256) void attn_kernel()
{
    int bh = blockIdx.x, jt = blockIdx.y, tid = threadIdx.x;
    int w = tid >> 5, lane = tid & 31;

    const uint4* kf = g_KF + ((bh*64 + jt*8 + w)*32 + lane)*2;
    uint4 khv = kf[0], klv = kf[1];
    u32 kh[4] = {khv.x, khv.y, khv.z, khv.w};
    u32 kl[4] = {klv.x, klv.y, klv.z, klv.w};

    const uint4* qf = g_QF + bh*128*32 + lane;
    const uint4* vf = g_VF + (bh*64*32 + lane)*2;

    float o0[4] = {}, o1[4] = {};
    float dg = 0.0f, d8 = 0.0f;

    #pragma unroll 2
    for (int c = 0; c < 64; c++) {
        uint4 q0 = qf[(2*c    )*32];
        uint4 q1 = qf[(2*c + 1)*32];
        uint4 va = vf[c*64];
        uint4 vb = vf[c*64 + 1];

        float sa[4] = {0.f,0.f,0.f,0.f}, sb[4] = {0.f,0.f,0.f,0.f};
        mma_bf16(sa, kh, q0.x, q0.y);
        mma_bf16(sa, kl, q0.x, q0.y);
        mma_bf16(sa, kh, q0.z, q0.w);
        mma_bf16(sb, kh, q1.x, q1.y);
        mma_bf16(sb, kl, q1.x, q1.y);
        mma_bf16(sb, kh, q1.z, q1.w);

        float pa0 = ex2(sa[0]), pa1 = ex2(sa[1]), pa2 = ex2(sa[2]), pa3 = ex2(sa[3]);
        float pb0 = ex2(sb[0]), pb1 = ex2(sb[1]), pb2 = ex2(sb[2]), pb3 = ex2(sb[3]);
        dg += (pa0 + pa1) + (pb0 + pb1);
        d8 += (pa2 + pa3) + (pb2 + pb3);

        u32 ph[4], pl[4];
        split2(pa0, pa1, ph[0], pl[0]);
        split2(pa2, pa3, ph[1], pl[1]);
        split2(pb0, pb1, ph[2], pl[2]);
        split2(pb2, pb3, ph[3], pl[3]);

        mma_bf16(o0, ph, va.x, va.y);
        mma_bf16(o0, pl, va.x, va.y);
        mma_bf16(o0, ph, vb.x, vb.y);
        mma_bf16(o1, ph, va.z, va.w);
        mma_bf16(o1, pl, va.z, va.w);
        mma_bf16(o1, ph, vb.z, vb.w);
    }

    dg += __shfl_xor_sync(0xFFFFFFFFu, dg, 1);
    dg += __shfl_xor_sync(0xFFFFFFFFu, dg, 2);
    d8 += __shfl_xor_sync(0xFFFFFFFFu, d8, 1);
    d8 += __shfl_xor_sync(0xFFFFFFFFu, d8, 2);
    float rg = 1.0f / dg, r8 = 1.0f / d8;

    int b = bh >> 3, h = bh & 7;
    int nb0 = jt*16 + w*2;
    uint4 o;
    split2(o0[0]*rg, o0[1]*rg, o.x, o.z);   // b0 of nb0 (v=2t,2t+1 @ col j0)
    split2(o1[0]*rg, o1[1]*rg, o.y, o.w);   // b1 of nb0 (v=2t+8,2t+9)
    g_HF[((b*8 + h)*128 + nb0)*32 + lane] = o;
    split2(o0[2]*r8, o0[3]*r8, o.x, o.z);   // b0 of nb1 (col j0+8)
    split2(o1[2]*r8, o1[3]*r8, o.y, o.w);
    g_HF[((b*8 + h)*128 + nb0 + 1)*32 + lane] = o;
}

// ---------------------------------------------------------------------------
// Kernel 5: outproj_mma — output projection on tensor cores.
// grid (8 b, 32 l-tiles of 32), 256 thr. Warp: M=64 (4 m-blocks) x N=8.
// ---------------------------------------------------------------------------
__global__ __launch_bounds__(256) void outproj_mma(float* __restrict__ out)
{
    int b = blockIdx.x, lt = blockIdx.y;
    int tid = threadIdx.x, w = tid >> 5, lane = tid & 31;
    int g = lane >> 2, t = lane & 3;
    int mh = w >> 2;            // 0: m-blocks 0-3, 1: m-blocks 4-7
    int nb = lt*4 + (w & 3);

    float acc[4][4] = {};
    #pragma unroll
    for (int kc = 0; kc < 8; kc++) {
        uint4 B = g_HF[((b*8 + kc)*128 + nb)*32 + lane];
        #pragma unroll
        for (int mi = 0; mi < 4; mi++) {
            const uint4* af = g_WoF + (((b*8 + mh*4 + mi)*8 + kc)*32 + lane)*2;
            uint4 Ah = af[0], Al = af[1];
            u32 ah[4] = {Ah.x, Ah.y, Ah.z, Ah.w};
            u32 al[4] = {Al.x, Al.y, Al.z, Al.w};
            mma_bf16(acc[mi], ah, B.x, B.y);
            mma_bf16(acc[mi], al, B.x, B.y);
            mma_bf16(acc[mi], ah, B.z, B.w);
        }
    }
    #pragma unroll
    for (int mi = 0; mi < 4; mi++) {
        int m0 = (mh*4 + mi)*16 + g;
        int col = nb*8 + 2*t;
        *(float2*)(out + (b*128 + m0    )*1024 + col) = make_float2(acc[mi][0], acc[mi][1]);
        *(float2*)(out + (b*128 + m0 + 8)*1024 + col) = make_float2(acc[mi][2], acc[mi][3]);
    }
}

// ---------------------------------------------------------------------------
extern "C" void kernel_launch(void* const* d_in, const int* in_sizes, int n_in,
                              void* d_out, int out_size)
{
    const float* x  = (const float*)d_in[0];
    const float* Wq = (const float*)d_in[1];
    const float* Wk = (const float*)d_in[2];
    const float* Wv = (const float*)d_in[3];
    const float* Wo = (const float*)d_in[4];
    float* out = (float*)d_out;

    prep_in<<<512, 256>>>(x, Wq, Wk, Wv, Wo);
    qkv_mma<<<dim3(64, 8), 256>>>();
    prep_attn<<<dim3(64, 8), 256>>>();
    attn_kernel<<<dim3(64, 8), 256>>>();
    outproj_mma<<<dim3(8, 32), 256>>>(out);
}